// round 14
// baseline (speedup 1.0000x reference)
#include <cuda_runtime.h>
#include <cuda_bf16.h>
#include <cstdint>

typedef unsigned char uchar;
typedef unsigned short ushort;
typedef __nv_bfloat16 bf16;

#define NB 8

// ---------------- device scratch ----------------
__device__ __align__(16) bf16 g_wk1[1024 * 1536];
__device__ __align__(16) bf16 g_wq1[160 * 240];
__device__ __align__(16) bf16 g_wk2[80 * 1024];
__device__ __align__(16) bf16 g_wq2[80 * 160];
__device__ __align__(16) bf16 g_wq3[80 * 80];
// 3 pre-shifted copies of each conv3 input: X3[kw][b][c][t] = Xpad[c][t+kw]
__device__ __align__(16) bf16 g_phonS [3 * NB * 512 * 264];   // XS=264
__device__ __align__(16) bf16 g_audioS[3 * NB * 80 * 1024];   // XS=1024
__device__ __align__(16) bf16 g_H1b[NB * 1024 * 256];
__device__ __align__(16) bf16 g_H2b[NB * 160 * 1000 + 64];
__device__ __align__(16) bf16 g_H3b[NB * 80 * 1000 + 64];
__device__ __align__(16) float g_keysP[4 * NB * 80 * 256];    // split-K partials
__device__ __align__(16) bf16  g_keysBf[NB * 80 * 256];
__device__ __align__(16) float g_Q[NB * 80 * 1000];
__device__ int g_maskmode;                                    // 0=u8, 1=i32, 2=f32

// ---------------- fused prep (4 elems/thread): convert + 3-shift pad + mask --
__global__ void prep_kernel(
    const float* __restrict__ kw1, const float* __restrict__ qw1,
    const float* __restrict__ kw2, const float* __restrict__ qw2,
    const float* __restrict__ qw3, const float* __restrict__ phon,
    const float* __restrict__ aud, const uchar* __restrict__ mask)
{
    if (blockIdx.x == 0 && threadIdx.x == 0) {
        const unsigned* d = (const unsigned*)mask;
        bool i32 = true, f32 = true;
        for (int i = 0; i < 256; i++) {
            unsigned v = d[i];
            if (v != 0u && v != 1u) i32 = false;
            if (v != 0u && v != 0x3F800000u) f32 = false;
        }
        g_maskmode = i32 ? 1 : (f32 ? 2 : 0);
    }
    long i = ((long)blockIdx.x * 256 + threadIdx.x) * 4;
    const long N1 = 1024L * 1536, N2 = 160 * 240, N3 = 80 * 1024,
               N4 = 80 * 160, N5 = 80 * 80;
    const long PCOPY = (long)NB * 512 * 264, PS = 3 * PCOPY;
    const long ACOPY = (long)NB * 80 * 1024, AS = 3 * ACOPY;

    const float* src = nullptr; bf16* dst = nullptr;
    if (i < N1) { src = kw1; dst = g_wk1; }
    else if ((i -= N1) < N2) { src = qw1; dst = g_wq1; }
    else if ((i -= N2) < N3) { src = kw2; dst = g_wk2; }
    else if ((i -= N3) < N4) { src = qw2; dst = g_wq2; }
    else if ((i -= N4) < N5) { src = qw3; dst = g_wq3; }
    if (src) {
        float4 v = *(const float4*)(src + i);
        *(__nv_bfloat162*)(dst + i)     = __floats2bfloat162_rn(v.x, v.y);
        *(__nv_bfloat162*)(dst + i + 2) = __floats2bfloat162_rn(v.z, v.w);
        return;
    }
    i -= N5;
    if (i < PS) {   // phonemes copies: [kw][r][t], t in rows of 264, valid x=t+kw in [1,256]
        int kw = (int)(i / PCOPY);
        long rem = i - (long)kw * PCOPY;
        long r = rem / 264; int t0e = (int)(rem - r * 264);
#pragma unroll
        for (int e = 0; e < 4; e++) {
            int x = t0e + e + kw;
            g_phonS[i + e] = (x >= 1 && x <= 256)
                ? __float2bfloat16(phon[r * 256 + x - 1]) : __float2bfloat16(0.f);
        }
        return;
    }
    i -= PS;
    if (i < AS) {   // audio copies: [kw][r][t], rows of 1024, valid x=t+kw in [1,1000]
        int kw = (int)(i / ACOPY);
        long rem = i - (long)kw * ACOPY;
        long r = rem / 1024; int t0e = (int)(rem - r * 1024);
#pragma unroll
        for (int e = 0; e < 4; e++) {
            int x = t0e + e + kw;
            g_audioS[i + e] = (x >= 1 && x <= 1000)
                ? __float2bfloat16(aud[r * 1000 + x - 1]) : __float2bfloat16(0.f);
        }
    }
}

// ---------------- mma helpers ----------------
__device__ __forceinline__ uint32_t smem_u32(const void* p) {
    return (uint32_t)__cvta_generic_to_shared(p);
}
__device__ __forceinline__ void ldsm4(uint32_t& r0, uint32_t& r1,
                                      uint32_t& r2, uint32_t& r3, uint32_t a) {
    asm volatile("ldmatrix.sync.aligned.m8n8.x4.shared.b16 {%0,%1,%2,%3}, [%4];"
                 : "=r"(r0), "=r"(r1), "=r"(r2), "=r"(r3) : "r"(a));
}
__device__ __forceinline__ void ldsm4t(uint32_t& r0, uint32_t& r1,
                                       uint32_t& r2, uint32_t& r3, uint32_t a) {
    asm volatile("ldmatrix.sync.aligned.m8n8.x4.trans.shared.b16 {%0,%1,%2,%3}, [%4];"
                 : "=r"(r0), "=r"(r1), "=r"(r2), "=r"(r3) : "r"(a));
}
__device__ __forceinline__ void mma16816(float c[4], const uint32_t a[4],
                                         uint32_t b0, uint32_t b1) {
    asm volatile(
        "mma.sync.aligned.m16n8k16.row.col.f32.bf16.bf16.f32 "
        "{%0,%1,%2,%3}, {%4,%5,%6,%7}, {%8,%9}, {%0,%1,%2,%3};"
        : "+f"(c[0]), "+f"(c[1]), "+f"(c[2]), "+f"(c[3])
        : "r"(a[0]), "r"(a[1]), "r"(a[2]), "r"(a[3]), "r"(b0), "r"(b1));
}

// ---------------- job descriptor ----------------
struct Job {
    const bf16* W; const float* bias; const bf16* X; char* Y;
    int M, T, XS, Ktot, kLen, nbx, nby, flags;  // flags: 1=relu, 2=outBf16, 4=split
    long cs;                                     // conv3: shift-copy stride (elems)
};

// ---------------------------------------------------------------------------
// Pipelined bf16 tensor-core conv-as-GEMM body (double-buffered, 1 sync/iter).
// KW=3: B row k = ci*3+kw reads pre-shifted copy kw -> fully vectorized.
// ---------------------------------------------------------------------------
template <int KW, int TKC, int TN, int WMI, int WNJ>
__device__ __forceinline__ void conv_body(const Job j, int bx, int by, int b)
{
    constexpr int TM = 128;
    constexpr int TK = TKC * KW;
    constexpr int KSTEPS = TK / 16;
    constexpr int ASTR = TK + 8;
    constexpr int BSTR = TN + 8;
    constexpr int WARPSN = TN / (16 * WNJ);
    constexpr int ACH = (TM * TK) / 2048;
    constexpr int AKCH = TK / 8;
    constexpr int BCH = (TK * TN) / 2048;       // uint4 chunks per thread (B)
    constexpr int BSEG = TN / 8;                // uint4 per B row

    extern __shared__ __align__(16) bf16 dsm[];
    bf16* Asm = dsm;
    bf16* Bsm = dsm + 2 * TM * ASTR;

    const bool relu = j.flags & 1, outBf = j.flags & 2, split = j.flags & 4;
    const int tid = threadIdx.x, lane = tid & 31, wid = tid >> 5;
    const int m0 = split ? 0 : by * TM;
    const int kb = split ? by * j.kLen : 0;
    const int kLim = min(kb + j.kLen, j.Ktot);
    const int Cin = j.Ktot / KW;
    const int t0 = bx * TN;
    const int wm = (wid / WARPSN) * (WMI * 16);
    const int wn = (wid % WARPSN) * (WNJ * 16);
    const bf16* Xb = j.X + (long)b * Cin * j.XS;
    const int Ktot = j.Ktot, M = j.M, T = j.T, XS = j.XS;

    const uint32_t AsU = smem_u32(Asm);
    const uint32_t BsU = smem_u32(Bsm);

    float acc[WMI][WNJ * 2][4];
#pragma unroll
    for (int mi = 0; mi < WMI; mi++)
#pragma unroll
        for (int jj = 0; jj < WNJ * 2; jj++)
#pragma unroll
            for (int c = 0; c < 4; c++) acc[mi][jj][c] = 0.f;

    const int iters = (kLim - kb + TK - 1) / TK;

    uint4 aR[ACH];
    uint4 bR[BCH];

    auto loadA = [&](int it) {
#pragma unroll
        for (int r = 0; r < ACH; r++) {
            int cid = tid + 256 * r;
            int row = cid / AKCH;
            int ch  = (cid % AKCH) * 8;
            int gm = m0 + row;
            int gk = kb + it * TK + ch;
            uint4 v = make_uint4(0u, 0u, 0u, 0u);
            if (gm < M && gk < kLim) v = *(const uint4*)(j.W + (long)gm * Ktot + gk);
            aR[r] = v;
        }
    };
    auto storeA = [&](int p) {
#pragma unroll
        for (int r = 0; r < ACH; r++) {
            int cid = tid + 256 * r;
            int row = cid / AKCH;
            int ch  = (cid % AKCH) * 8;
            *(uint4*)(Asm + p * TM * ASTR + row * ASTR + ch) = aR[r];
        }
    };
    auto loadB = [&](int it) {
#pragma unroll
        for (int r = 0; r < BCH; r++) {
            int cid = tid + 256 * r;
            int row = cid / BSEG, seg = cid % BSEG;
            int gk = kb + it * TK + row;
            if constexpr (KW == 1) {
                uint4 v = make_uint4(0u, 0u, 0u, 0u);
                if (gk < kLim) v = *(const uint4*)(Xb + (long)gk * XS + t0 + seg * 8);
                bR[r] = v;
            } else {
                int ci = gk / 3, kw = gk - 3 * ci;   // K multiple of TK: gk always valid
                bR[r] = *(const uint4*)(Xb + (long)kw * j.cs + (long)ci * XS + t0 + seg * 8);
            }
        }
    };
    auto storeB = [&](int p) {
#pragma unroll
        for (int r = 0; r < BCH; r++) {
            int cid = tid + 256 * r;
            int row = cid / BSEG, seg = cid % BSEG;
            *(uint4*)(Bsm + p * TK * BSTR + row * BSTR + seg * 8) = bR[r];
        }
    };
    auto compute = [&](int p) {
#pragma unroll
        for (int ks = 0; ks < KSTEPS; ks++) {
            uint32_t a[WMI][4];
#pragma unroll
            for (int mi = 0; mi < WMI; mi++) {
                uint32_t addr = AsU + (uint32_t)(p * TM * ASTR +
                    (wm + mi * 16 + (lane & 15)) * ASTR + ks * 16 + (lane >> 4) * 8) * 2;
                ldsm4(a[mi][0], a[mi][1], a[mi][2], a[mi][3], addr);
            }
            uint32_t bb[WNJ][4];
#pragma unroll
            for (int nj = 0; nj < WNJ; nj++) {
                uint32_t addr = BsU + (uint32_t)(p * TK * BSTR +
                    (ks * 16 + (lane & 15)) * BSTR + wn + nj * 16 + (lane >> 4) * 8) * 2;
                ldsm4t(bb[nj][0], bb[nj][1], bb[nj][2], bb[nj][3], addr);
            }
#pragma unroll
            for (int mi = 0; mi < WMI; mi++)
#pragma unroll
                for (int nj = 0; nj < WNJ; nj++) {
                    mma16816(acc[mi][nj * 2 + 0], a[mi], bb[nj][0], bb[nj][1]);
                    mma16816(acc[mi][nj * 2 + 1], a[mi], bb[nj][2], bb[nj][3]);
                }
        }
    };

    loadA(0); loadB(0);
    storeA(0); storeB(0);
    __syncthreads();
    for (int it = 0; it < iters; it++) {
        int p = it & 1;
        if (it + 1 < iters) { loadA(it + 1); loadB(it + 1); }
        compute(p);
        if (it + 1 < iters) {
            storeA(1 - p); storeB(1 - p);
            __syncthreads();
        }
    }

    const int g = lane >> 2, tig = lane & 3;
#pragma unroll
    for (int mi = 0; mi < WMI; mi++)
#pragma unroll
        for (int h = 0; h < 2; h++) {
            int gm = m0 + wm + mi * 16 + g + h * 8;
            if (gm >= M) continue;
            float bv = (split && by != 0) ? 0.f : j.bias[gm];
            long rowoff;
            if (split) rowoff = ((long)(by * NB + b) * M + gm) * T;
            else       rowoff = ((long)b * M + gm) * T;
#pragma unroll
            for (int jj = 0; jj < WNJ * 2; jj++) {
                int t = t0 + wn + jj * 8 + tig * 2;
                if (t >= T) continue;
                float v0 = acc[mi][jj][h * 2 + 0] + bv;
                float v1 = acc[mi][jj][h * 2 + 1] + bv;
                if (relu) { v0 = fmaxf(v0, 0.f); v1 = fmaxf(v1, 0.f); }
                if (outBf)
                    *(__nv_bfloat162*)((bf16*)j.Y + rowoff + t) = __floats2bfloat162_rn(v0, v1);
                else
                    *(float2*)((float*)j.Y + rowoff + t) = make_float2(v0, v1);
            }
        }
}

__device__ __forceinline__ void decode(const Job& j, int local, int& bx, int& by, int& bz)
{
    bx = local % j.nbx;
    int rem = local / j.nbx;
    by = rem % j.nby;
    bz = rem / j.nby;
}

// L2: both k=3 convs in one launch (TN=128, warp tile 64x32; vectorized B)
__global__ void __launch_bounds__(256) conv3_dual(Job j0, Job j1, int n0)
{
    int bid = blockIdx.x;
    Job j = (bid < n0) ? j0 : j1;
    int local = (bid < n0) ? bid : bid - n0;
    int bx, by, bz; decode(j, local, bx, by, bz);
    conv_body<3, 16, 128, 4, 2>(j, bx, by, bz);
}

// L3/L4: 1x1 convs (+ optional keys split-K reduce blocks at the tail)
__global__ void __launch_bounds__(256) conv1_multi(Job j0, Job j1, int n0, int ntot, int nParts)
{
    int bid = blockIdx.x;
    if (bid >= ntot) {      // reduce blocks
        int i = ((bid - ntot) * 256 + threadIdx.x) * 4;
        const int N = NB * 80 * 256;
        if (i < N) {
            float4 s = *(const float4*)&g_keysP[i];
            for (int p = 1; p < nParts; p++) {
                float4 t = *(const float4*)&g_keysP[(long)p * N + i];
                s.x += t.x; s.y += t.y; s.z += t.z; s.w += t.w;
            }
            __nv_bfloat162* dst = (__nv_bfloat162*)&g_keysBf[i];
            dst[0] = __floats2bfloat162_rn(s.x, s.y);
            dst[1] = __floats2bfloat162_rn(s.z, s.w);
        }
        return;
    }
    Job j = (bid < n0) ? j0 : j1;
    int local = (bid < n0) ? bid : bid - n0;
    int bx, by, bz; decode(j, local, bx, by, bz);
    conv_body<1, 32, 64, 2, 2>(j, bx, by, bz);
}

// ---------------------------------------------------------------------------
// attention: out = log_softmax(-T*|q-k|^2) + log(prior+1e-8); !mask -> -inf.
// ---------------------------------------------------------------------------
__global__ void __launch_bounds__(256) attn_kernel(
    const float* __restrict__ prior, const void* __restrict__ maskraw,
    float* __restrict__ out)
{
    __shared__ __align__(16) bf16 ks[80 * 256];
    __shared__ float k2s[256];
    __shared__ float qs[8 * 80];

    const int b = blockIdx.y;
    const int tid = threadIdx.x;
    const int mode = g_maskmode;
    const bf16* keysb = g_keysBf + (long)b * 80 * 256;

    for (int i = tid; i < 80 * 256 / 8; i += 256)
        ((uint4*)ks)[i] = ((const uint4*)keysb)[i];
    __syncthreads();
    {
        int t = tid;
        float s = 0.f;
#pragma unroll 8
        for (int c = 0; c < 80; c++) {
            float v = __bfloat162float(ks[c * 256 + t]);
            s += v * v;
        }
        k2s[t] = s;
    }
    __syncthreads();

    const int wid = tid >> 5, lane = tid & 31;
    for (int it = 0; it < 5; it++) {
        int row = blockIdx.x * 40 + it * 8 + wid;
        for (int c = lane; c < 80; c += 32)
            qs[wid * 80 + c] = g_Q[((long)b * 80 + c) * 1000 + row];
        __syncwarp();

        float acc[8];
#pragma unroll
        for (int j = 0; j < 8; j++) acc[j] = 0.f;
#pragma unroll 4
        for (int c = 0; c < 80; c++) {
            float qv = qs[wid * 80 + c];
            uint4 kv = *(const uint4*)&ks[c * 256 + lane * 8];
            float2 f0 = __bfloat1622float2(*(__nv_bfloat162*)&kv.x);
            float2 f1 = __bfloat1622float2(*(__nv_bfloat162*)&kv.y);
            float2 f2 = __bfloat1622float2(*(__nv_bfloat162*)&kv.z);
            float2 f3 = __bfloat1622float2(*(__nv_bfloat162*)&kv.w);
            acc[0] += qv * f0.x; acc[1] += qv * f0.y;
            acc[2] += qv * f1.x; acc[3] += qv * f1.y;
            acc[4] += qv * f2.x; acc[5] += qv * f2.y;
            acc[6] += qv * f3.x; acc[7] += qv * f3.y;
        }

        float s[8];
        float mx = -1e30f;
#pragma unroll
        for (int j = 0; j < 8; j++) {
            s[j] = 0.0005f * (2.f * acc[j] - k2s[lane * 8 + j]);
            mx = fmaxf(mx, s[j]);
        }
#pragma unroll
        for (int o = 16; o > 0; o >>= 1) mx = fmaxf(mx, __shfl_xor_sync(0xffffffffu, mx, o));
        float sum = 0.f;
#pragma unroll
        for (int j = 0; j < 8; j++) sum += __expf(s[j] - mx);
#pragma unroll
        for (int o = 16; o > 0; o >>= 1) sum += __shfl_xor_sync(0xffffffffu, sum, o);
        float lse = mx + __logf(sum);

        long base = ((long)(b * 1000 + row)) * 256 + lane * 8;
        float4 p0 = *(const float4*)(prior + base);
        float4 p1 = *(const float4*)(prior + base + 4);
        const float NEG = __int_as_float(0xff800000);
        float o8[8];
        o8[0] = s[0] - lse + __logf(p0.x + 1e-8f);
        o8[1] = s[1] - lse + __logf(p0.y + 1e-8f);
        o8[2] = s[2] - lse + __logf(p0.z + 1e-8f);
        o8[3] = s[3] - lse + __logf(p0.w + 1e-8f);
        o8[4] = s[4] - lse + __logf(p1.x + 1e-8f);
        o8[5] = s[5] - lse + __logf(p1.y + 1e-8f);
        o8[6] = s[6] - lse + __logf(p1.z + 1e-8f);
        o8[7] = s[7] - lse + __logf(p1.w + 1e-8f);

        if (mode == 1) {
            const int* mp = (const int*)maskraw;
#pragma unroll
            for (int j = 0; j < 8; j++) if (mp[base + j] == 0) o8[j] = NEG;
        } else if (mode == 2) {
            const float* mp = (const float*)maskraw;
#pragma unroll
            for (int j = 0; j < 8; j++) if (mp[base + j] == 0.f) o8[j] = NEG;
        } else {
            const uchar* mp = (const uchar*)maskraw;
            uchar4 m0 = *(const uchar4*)(mp + base);
            uchar4 m1 = *(const uchar4*)(mp + base + 4);
            if (!m0.x) o8[0] = NEG; if (!m0.y) o8[1] = NEG;
            if (!m0.z) o8[2] = NEG; if (!m0.w) o8[3] = NEG;
            if (!m1.x) o8[4] = NEG; if (!m1.y) o8[5] = NEG;
            if (!m1.z) o8[6] = NEG; if (!m1.w) o8[7] = NEG;
        }

        *(float4*)(out + base)     = make_float4(o8[0], o8[1], o8[2], o8[3]);
        *(float4*)(out + base + 4) = make_float4(o8[4], o8[5], o8[6], o8[7]);
        __syncwarp();
    }
}

// ---------------------------------------------------------------------------
extern "C" void kernel_launch(void* const* d_in, const int* in_sizes, int n_in,
                              void* d_out, int out_size)
{
    const float* phonemes = (const float*)d_in[0];
    const float* audio    = (const float*)d_in[1];
    const uchar* mask     = (const uchar*)d_in[2];
    const float* prior    = (const float*)d_in[3];
    const float* kw1 = (const float*)d_in[4];
    const float* kb1 = (const float*)d_in[5];
    const float* kw2 = (const float*)d_in[6];
    const float* kb2 = (const float*)d_in[7];
    const float* qw1 = (const float*)d_in[8];
    const float* qb1 = (const float*)d_in[9];
    const float* qw2 = (const float*)d_in[10];
    const float* qb2 = (const float*)d_in[11];
    const float* qw3 = (const float*)d_in[12];
    const float* qb3 = (const float*)d_in[13];
    float* out = (float*)d_out;

    void* p;
    cudaGetSymbolAddress(&p, g_wk1);    bf16* wk1 = (bf16*)p;
    cudaGetSymbolAddress(&p, g_wq1);    bf16* wq1 = (bf16*)p;
    cudaGetSymbolAddress(&p, g_wk2);    bf16* wk2 = (bf16*)p;
    cudaGetSymbolAddress(&p, g_wq2);    bf16* wq2 = (bf16*)p;
    cudaGetSymbolAddress(&p, g_wq3);    bf16* wq3 = (bf16*)p;
    cudaGetSymbolAddress(&p, g_phonS);  bf16* phonS = (bf16*)p;
    cudaGetSymbolAddress(&p, g_audioS); bf16* audS  = (bf16*)p;
    cudaGetSymbolAddress(&p, g_H1b);    bf16* H1 = (bf16*)p;
    cudaGetSymbolAddress(&p, g_H2b);    bf16* H2 = (bf16*)p;
    cudaGetSymbolAddress(&p, g_H3b);    bf16* H3 = (bf16*)p;
    cudaGetSymbolAddress(&p, g_keysP);  float* keysP = (float*)p;
    cudaGetSymbolAddress(&p, g_Q);      float* Q = (float*)p;

    const int SMEM_K3 = (2 * 128 * 56 + 2 * 48 * 136) * 2;  // 54784
    const int SMEM_K1 = (2 * 128 * 40 + 2 * 32 * 72) * 2;   // 29696

    cudaFuncSetAttribute(conv3_dual,
                         cudaFuncAttributeMaxDynamicSharedMemorySize, SMEM_K3);

    // L1: prep (weights + 3-shift input copies + mask detect)
    {
        long total = 1024L * 1536 + 160 * 240 + 80 * 1024 + 80 * 160 + 80 * 80
                   + 3L * NB * 512 * 264 + 3L * NB * 80 * 1024;
        prep_kernel<<<(int)((total / 4 + 255) / 256), 256>>>(
            kw1, qw1, kw2, qw2, qw3, phonemes, audio, mask);
    }

    // L2: kconv1 + qconv1 merged (TN=128 config; vectorized shift-copy B)
    {
        Job jk1 = { wk1, kb1, phonS, (char*)H1, 1024, 256, 264, 1536, 1536,
                    2, 8, 1 | 2, (long)NB * 512 * 264 };
        Job jq1 = { wq1, qb1, audS,  (char*)H2, 160, 1000, 1024, 240, 240,
                    8, 2, 1 | 2, (long)NB * 80 * 1024 };
        conv3_dual<<<128 + 128, 256, SMEM_K3>>>(jk1, jq1, 128);
    }

    // L3: kconv2 split-K x4 + qconv2 (merged)
    {
        Job jk2 = { wk2, kb2, H1, (char*)keysP, 80, 256, 256, 1024, 256, 4, 4, 4, 0 };
        Job jq2 = { wq2, qb2, H2, (char*)H3, 80, 1000, 1000, 160, 160, 16, 1, 1 | 2, 0 };
        conv1_multi<<<128 + 128, 256, SMEM_K1>>>(jk2, jq2, 128, 256, 0);
    }

    // L4: qconv3 + keys reduce x4 (merged)
    {
        Job jq3 = { wq3, qb3, H3, (char*)Q, 80, 1000, 1000, 80, 80, 16, 1, 0, 0 };
        conv1_multi<<<128 + 160, 256, SMEM_K1>>>(jq3, jq3, 128, 128, 4);
    }

    // L5: attention + log_softmax + prior + mask
    attn_kernel<<<dim3(25, 8), 256>>>(prior, mask, out);
}

// round 16
// speedup vs baseline: 1.0870x; 1.0870x over previous
#include <cuda_runtime.h>
#include <cuda_bf16.h>
#include <cstdint>

typedef unsigned char uchar;
typedef unsigned short ushort;
typedef __nv_bfloat16 bf16;

#define NB 8

// ---------------- device scratch ----------------
__device__ __align__(16) bf16 g_wk1[1024 * 1536];
__device__ __align__(16) bf16 g_wq1[160 * 240];
__device__ __align__(16) bf16 g_wk2[80 * 1024];
__device__ __align__(16) bf16 g_wq2[80 * 160];
__device__ __align__(16) bf16 g_wq3[80 * 80];
__device__ __align__(16) bf16 g_phon [NB * 512 * 272];     // halo-padded, XS=272
__device__ __align__(16) bf16 g_audio[NB * 80 * 1040];     // halo-padded, XS=1040
__device__ __align__(16) bf16 g_H1b[NB * 1024 * 256];
__device__ __align__(16) bf16 g_H2b[NB * 160 * 1000 + 64];
__device__ __align__(16) bf16 g_H3b[NB * 80 * 1000 + 64];
__device__ __align__(16) float g_keysP[4 * NB * 80 * 256]; // split-K partials (x4)
__device__ __align__(16) bf16  g_keysBf[NB * 80 * 256];
__device__ __align__(16) float g_Q[NB * 80 * 1000];
__device__ int g_maskmode;                                 // 0=u8, 1=i32, 2=f32

union U8 { uint4 v; ushort u[8]; };

// ---------------- fused prep (4 elems/thread): convert + pad + mask detect --
__global__ void prep_kernel(
    const float* __restrict__ kw1, const float* __restrict__ qw1,
    const float* __restrict__ kw2, const float* __restrict__ qw2,
    const float* __restrict__ qw3, const float* __restrict__ phon,
    const float* __restrict__ aud, const uchar* __restrict__ mask)
{
    if (blockIdx.x == 0 && threadIdx.x == 0) {
        const unsigned* d = (const unsigned*)mask;
        bool i32 = true, f32 = true;
        for (int i = 0; i < 256; i++) {
            unsigned v = d[i];
            if (v != 0u && v != 1u) i32 = false;
            if (v != 0u && v != 0x3F800000u) f32 = false;
        }
        g_maskmode = i32 ? 1 : (f32 ? 2 : 0);
    }
    long i = ((long)blockIdx.x * 256 + threadIdx.x) * 4;
    const long N1 = 1024L * 1536, N2 = 160 * 240, N3 = 80 * 1024,
               N4 = 80 * 160, N5 = 80 * 80;
    const long NP = 8L * 512 * 272, NA = 8L * 80 * 1040;

    const float* src = nullptr; bf16* dst = nullptr;
    if (i < N1) { src = kw1; dst = g_wk1; }
    else if ((i -= N1) < N2) { src = qw1; dst = g_wq1; }
    else if ((i -= N2) < N3) { src = kw2; dst = g_wk2; }
    else if ((i -= N3) < N4) { src = qw2; dst = g_wq2; }
    else if ((i -= N4) < N5) { src = qw3; dst = g_wq3; }
    if (src) {
        float4 v = *(const float4*)(src + i);
        *(__nv_bfloat162*)(dst + i)     = __floats2bfloat162_rn(v.x, v.y);
        *(__nv_bfloat162*)(dst + i + 2) = __floats2bfloat162_rn(v.z, v.w);
        return;
    }
    i -= N5;
    if (i < NP) {   // phonemes: rows of 272, valid x in [1,256]
        long r = i / 272; int x0 = (int)(i - r * 272);
#pragma unroll
        for (int e = 0; e < 4; e++) {
            int x = x0 + e;
            g_phon[i + e] = (x >= 1 && x <= 256)
                ? __float2bfloat16(phon[r * 256 + x - 1]) : __float2bfloat16(0.f);
        }
        return;
    }
    i -= NP;
    if (i < NA) {   // audio: rows of 1040, valid x in [1,1000]
        long r = i / 1040; int x0 = (int)(i - r * 1040);
#pragma unroll
        for (int e = 0; e < 4; e++) {
            int x = x0 + e;
            g_audio[i + e] = (x >= 1 && x <= 1000)
                ? __float2bfloat16(aud[r * 1000 + x - 1]) : __float2bfloat16(0.f);
        }
    }
}

// ---------------- mma / cp.async helpers ----------------
__device__ __forceinline__ uint32_t smem_u32(const void* p) {
    return (uint32_t)__cvta_generic_to_shared(p);
}
__device__ __forceinline__ void cpasync16(uint32_t dst, const void* src, int szbytes) {
    asm volatile("cp.async.cg.shared.global [%0], [%1], 16, %2;"
                 :: "r"(dst), "l"(src), "r"(szbytes) : "memory");
}
#define CP_COMMIT() asm volatile("cp.async.commit_group;" ::: "memory")
#define CP_WAIT0()  asm volatile("cp.async.wait_group 0;" ::: "memory")

__device__ __forceinline__ void ldsm4(uint32_t& r0, uint32_t& r1,
                                      uint32_t& r2, uint32_t& r3, uint32_t a) {
    asm volatile("ldmatrix.sync.aligned.m8n8.x4.shared.b16 {%0,%1,%2,%3}, [%4];"
                 : "=r"(r0), "=r"(r1), "=r"(r2), "=r"(r3) : "r"(a));
}
__device__ __forceinline__ void ldsm4t(uint32_t& r0, uint32_t& r1,
                                       uint32_t& r2, uint32_t& r3, uint32_t a) {
    asm volatile("ldmatrix.sync.aligned.m8n8.x4.trans.shared.b16 {%0,%1,%2,%3}, [%4];"
                 : "=r"(r0), "=r"(r1), "=r"(r2), "=r"(r3) : "r"(a));
}
__device__ __forceinline__ void mma16816(float c[4], const uint32_t a[4],
                                         uint32_t b0, uint32_t b1) {
    asm volatile(
        "mma.sync.aligned.m16n8k16.row.col.f32.bf16.bf16.f32 "
        "{%0,%1,%2,%3}, {%4,%5,%6,%7}, {%8,%9}, {%0,%1,%2,%3};"
        : "+f"(c[0]), "+f"(c[1]), "+f"(c[2]), "+f"(c[3])
        : "r"(a[0]), "r"(a[1]), "r"(a[2]), "r"(a[3]), "r"(b0), "r"(b1));
}

template <int BSTR, int TN>
__device__ __forceinline__ void storeB3(ushort* Brow, int pbase, uint4 v) {
    U8 u; u.v = v;
#pragma unroll
    for (int kw = 0; kw < 3; kw++)
#pragma unroll
        for (int j = 0; j < 8; j++) {
            int t = pbase + j - kw;
            if (t >= 0 && t < TN) Brow[kw * BSTR + t] = u.u[j];
        }
}

// ---------------- job descriptor ----------------
struct Job {
    const bf16* W; const float* bias; const bf16* X; char* Y;
    int M, T, XS, Ktot, kLen, nbx, nby, flags;  // flags: 1=relu, 2=outBf16, 4=split
};

// ---------------------------------------------------------------------------
// Pipelined bf16 tensor-core conv-as-GEMM body.
// A staging (and B staging for KW=1) now via cp.async: copies for it+1 are
// issued before compute(it) and land during it; no register round-trip, no
// post-compute STS burst on the critical path.
// ---------------------------------------------------------------------------
template <int KW, int TKC, int TN, int WMI, int WNJ>
__device__ __forceinline__ void conv_body(const Job j, int bx, int by, int b)
{
    constexpr int TM = 128;
    constexpr int TK = TKC * KW;
    constexpr int KSTEPS = TK / 16;
    constexpr int ASTR = TK + 8;
    constexpr int BSTR = TN + 8;
    constexpr int WARPSN = TN / (16 * WNJ);
    constexpr int ACH = (TM * TK) / 2048;
    constexpr int AKCH = TK / 8;

    extern __shared__ __align__(16) bf16 dsm[];
    bf16* Asm = dsm;
    bf16* Bsm = dsm + 2 * TM * ASTR;

    const bool relu = j.flags & 1, outBf = j.flags & 2, split = j.flags & 4;
    const int tid = threadIdx.x, lane = tid & 31, wid = tid >> 5;
    const int m0 = split ? 0 : by * TM;
    const int kb = split ? by * j.kLen : 0;
    const int kLim = min(kb + j.kLen, j.Ktot);
    const int Cin = j.Ktot / KW;
    const int t0 = bx * TN;
    const int wm = (wid / WARPSN) * (WMI * 16);
    const int wn = (wid % WARPSN) * (WNJ * 16);
    const bf16* Xb = j.X + (long)b * Cin * j.XS;
    const int Ktot = j.Ktot, M = j.M, T = j.T, XS = j.XS;

    const uint32_t AsU = smem_u32(Asm);
    const uint32_t BsU = smem_u32(Bsm);

    float acc[WMI][WNJ * 2][4];
#pragma unroll
    for (int mi = 0; mi < WMI; mi++)
#pragma unroll
        for (int jj = 0; jj < WNJ * 2; jj++)
#pragma unroll
            for (int c = 0; c < 4; c++) acc[mi][jj][c] = 0.f;

    const int iters = (kLim - kb + TK - 1) / TK;

    uint4 bR0, bR1;
    constexpr int CHB = (TN + 16) / 8;

    // A staging: cp.async (zfill when out of range)
    auto issueA = [&](int it, int p) {
#pragma unroll
        for (int r = 0; r < ACH; r++) {
            int cid = tid + 256 * r;
            int row = cid / AKCH;
            int ch  = (cid % AKCH) * 8;
            int gm = m0 + row;
            int gk = kb + it * TK + ch;
            bool ok = (gm < M && gk < kLim);
            const bf16* src = j.W + (ok ? ((long)gm * Ktot + gk) : 0);
            cpasync16(AsU + (uint32_t)(p * TM * ASTR + row * ASTR + ch) * 2,
                      src, ok ? 16 : 0);
        }
    };
    // B staging: cp.async for KW==1; register + shifted scalar stores for KW==3
    auto issueB1 = [&](int it, int p) {
        int kk = tid >> 3, seg = tid & 7;
        int c = kb + it * TK + kk;
        bool ok = (c < kLim);
        const bf16* src = Xb + (ok ? ((long)c * XS + t0 + seg * 8) : 0);
        cpasync16(BsU + (uint32_t)(p * TK * BSTR + kk * BSTR + seg * 8) * 2,
                  src, ok ? 16 : 0);
    };
    auto loadB3 = [&](int it) {
        int r = tid >> 4, seg = tid & 15;
        const bf16* rowp = Xb + (long)(it * TKC + r) * XS + t0;
        if (seg < CHB) bR0 = *(const uint4*)(rowp + seg * 8);
        if constexpr (CHB > 16) {
            if (seg + 16 < CHB) bR1 = *(const uint4*)(rowp + (seg + 16) * 8);
        }
    };
    auto storeB3s = [&](int p) {
        int r = tid >> 4, seg = tid & 15;
        ushort* Brow = (ushort*)(Bsm + p * TK * BSTR + (r * 3) * BSTR);
        if (seg < CHB) storeB3<BSTR, TN>(Brow, seg * 8, bR0);
        if constexpr (CHB > 16) {
            if (seg + 16 < CHB) storeB3<BSTR, TN>(Brow, (seg + 16) * 8, bR1);
        }
    };
    auto compute = [&](int p) {
#pragma unroll
        for (int ks = 0; ks < KSTEPS; ks++) {
            uint32_t a[WMI][4];
#pragma unroll
            for (int mi = 0; mi < WMI; mi++) {
                uint32_t addr = AsU + (uint32_t)(p * TM * ASTR +
                    (wm + mi * 16 + (lane & 15)) * ASTR + ks * 16 + (lane >> 4) * 8) * 2;
                ldsm4(a[mi][0], a[mi][1], a[mi][2], a[mi][3], addr);
            }
            uint32_t bb[WNJ][4];
#pragma unroll
            for (int nj = 0; nj < WNJ; nj++) {
                uint32_t addr = BsU + (uint32_t)(p * TK * BSTR +
                    (ks * 16 + (lane & 15)) * BSTR + wn + nj * 16 + (lane >> 4) * 8) * 2;
                ldsm4t(bb[nj][0], bb[nj][1], bb[nj][2], bb[nj][3], addr);
            }
#pragma unroll
            for (int mi = 0; mi < WMI; mi++)
#pragma unroll
                for (int nj = 0; nj < WNJ; nj++) {
                    mma16816(acc[mi][nj * 2 + 0], a[mi], bb[nj][0], bb[nj][1]);
                    mma16816(acc[mi][nj * 2 + 1], a[mi], bb[nj][2], bb[nj][3]);
                }
        }
    };

    // prologue
    issueA(0, 0);
    if constexpr (KW == 1) issueB1(0, 0); else loadB3(0);
    CP_COMMIT();
    if constexpr (KW == 3) storeB3s(0);
    CP_WAIT0();
    __syncthreads();

    for (int it = 0; it < iters; it++) {
        int p = it & 1;
        if (it + 1 < iters) {
            issueA(it + 1, 1 - p);
            if constexpr (KW == 1) issueB1(it + 1, 1 - p); else loadB3(it + 1);
            CP_COMMIT();
        }
        compute(p);
        if (it + 1 < iters) {
            if constexpr (KW == 3) storeB3s(1 - p);
            CP_WAIT0();
            __syncthreads();
        }
    }

    // epilogue
    const int g = lane >> 2, tig = lane & 3;
#pragma unroll
    for (int mi = 0; mi < WMI; mi++)
#pragma unroll
        for (int h = 0; h < 2; h++) {
            int gm = m0 + wm + mi * 16 + g + h * 8;
            if (gm >= M) continue;
            float bv = (split && by != 0) ? 0.f : j.bias[gm];
            long rowoff;
            if (split) rowoff = ((long)(by * NB + b) * M + gm) * T;
            else       rowoff = ((long)b * M + gm) * T;
#pragma unroll
            for (int jj = 0; jj < WNJ * 2; jj++) {
                int t = t0 + wn + jj * 8 + tig * 2;
                if (t >= T) continue;
                float v0 = acc[mi][jj][h * 2 + 0] + bv;
                float v1 = acc[mi][jj][h * 2 + 1] + bv;
                if (relu) { v0 = fmaxf(v0, 0.f); v1 = fmaxf(v1, 0.f); }
                if (outBf)
                    *(__nv_bfloat162*)((bf16*)j.Y + rowoff + t) = __floats2bfloat162_rn(v0, v1);
                else
                    *(float2*)((float*)j.Y + rowoff + t) = make_float2(v0, v1);
            }
        }
}

__device__ __forceinline__ void decode(const Job& j, int local, int& bx, int& by, int& bz)
{
    bx = local % j.nbx;
    int rem = local / j.nbx;
    by = rem % j.nby;
    bz = rem / j.nby;
}

// L2: both k=3 convs in one launch (R12-proven TN=128, warp tile 64x32)
__global__ void __launch_bounds__(256) conv3_dual(Job j0, Job j1, int n0)
{
    int bid = blockIdx.x;
    Job j = (bid < n0) ? j0 : j1;
    int local = (bid < n0) ? bid : bid - n0;
    int bx, by, bz; decode(j, local, bx, by, bz);
    conv_body<3, 16, 128, 4, 2>(j, bx, by, bz);
}

// L3/L4: 1x1 convs (+ optional keys split-K reduce blocks at the tail)
__global__ void __launch_bounds__(256) conv1_multi(Job j0, Job j1, int n0, int ntot, int nParts)
{
    int bid = blockIdx.x;
    if (bid >= ntot) {      // reduce blocks
        int i = ((bid - ntot) * 256 + threadIdx.x) * 4;
        const int N = NB * 80 * 256;
        if (i < N) {
            float4 s = *(const float4*)&g_keysP[i];
            for (int p = 1; p < nParts; p++) {
                float4 t = *(const float4*)&g_keysP[(long)p * N + i];
                s.x += t.x; s.y += t.y; s.z += t.z; s.w += t.w;
            }
            __nv_bfloat162* dst = (__nv_bfloat162*)&g_keysBf[i];
            dst[0] = __floats2bfloat162_rn(s.x, s.y);
            dst[1] = __floats2bfloat162_rn(s.z, s.w);
        }
        return;
    }
    Job j = (bid < n0) ? j0 : j1;
    int local = (bid < n0) ? bid : bid - n0;
    int bx, by, bz; decode(j, local, bx, by, bz);
    conv_body<1, 32, 64, 2, 2>(j, bx, by, bz);
}

// ---------------------------------------------------------------------------
// attention: out = log_softmax(-T*|q-k|^2) + log(prior+1e-8); !mask -> -inf.
// ---------------------------------------------------------------------------
__global__ void __launch_bounds__(256) attn_kernel(
    const float* __restrict__ prior, const void* __restrict__ maskraw,
    float* __restrict__ out)
{
    __shared__ __align__(16) bf16 ks[80 * 256];
    __shared__ float k2s[256];
    __shared__ float qs[8 * 80];

    const int b = blockIdx.y;
    const int tid = threadIdx.x;
    const int mode = g_maskmode;
    const bf16* keysb = g_keysBf + (long)b * 80 * 256;

    for (int i = tid; i < 80 * 256 / 8; i += 256)
        ((uint4*)ks)[i] = ((const uint4*)keysb)[i];
    __syncthreads();
    {
        int t = tid;
        float s = 0.f;
#pragma unroll 8
        for (int c = 0; c < 80; c++) {
            float v = __bfloat162float(ks[c * 256 + t]);
            s += v * v;
        }
        k2s[t] = s;
    }
    __syncthreads();

    const int wid = tid >> 5, lane = tid & 31;
    for (int it = 0; it < 5; it++) {
        int row = blockIdx.x * 40 + it * 8 + wid;
        for (int c = lane; c < 80; c += 32)
            qs[wid * 80 + c] = g_Q[((long)b * 80 + c) * 1000 + row];
        __syncwarp();

        float acc[8];
#pragma unroll
        for (int j = 0; j < 8; j++) acc[j] = 0.f;
#pragma unroll 4
        for (int c = 0; c < 80; c++) {
            float qv = qs[wid * 80 + c];
            uint4 kv = *(const uint4*)&ks[c * 256 + lane * 8];
            float2 f0 = __bfloat1622float2(*(__nv_bfloat162*)&kv.x);
            float2 f1 = __bfloat1622float2(*(__nv_bfloat162*)&kv.y);
            float2 f2 = __bfloat1622float2(*(__nv_bfloat162*)&kv.z);
            float2 f3 = __bfloat1622float2(*(__nv_bfloat162*)&kv.w);
            acc[0] += qv * f0.x; acc[1] += qv * f0.y;
            acc[2] += qv * f1.x; acc[3] += qv * f1.y;
            acc[4] += qv * f2.x; acc[5] += qv * f2.y;
            acc[6] += qv * f3.x; acc[7] += qv * f3.y;
        }

        float s[8];
        float mx = -1e30f;
#pragma unroll
        for (int j = 0; j < 8; j++) {
            s[j] = 0.0005f * (2.f * acc[j] - k2s[lane * 8 + j]);
            mx = fmaxf(mx, s[j]);
        }
#pragma unroll
        for (int o = 16; o > 0; o >>= 1) mx = fmaxf(mx, __shfl_xor_sync(0xffffffffu, mx, o));
        float sum = 0.f;
#pragma unroll
        for (int j = 0; j < 8; j++) sum += __expf(s[j] - mx);
#pragma unroll
        for (int o = 16; o > 0; o >>= 1) sum += __shfl_xor_sync(0xffffffffu, sum, o);
        float lse = mx + __logf(sum);

        long base = ((long)(b * 1000 + row)) * 256 + lane * 8;
        float4 p0 = *(const float4*)(prior + base);
        float4 p1 = *(const float4*)(prior + base + 4);
        const float NEG = __int_as_float(0xff800000);
        float o8[8];
        o8[0] = s[0] - lse + __logf(p0.x + 1e-8f);
        o8[1] = s[1] - lse + __logf(p0.y + 1e-8f);
        o8[2] = s[2] - lse + __logf(p0.z + 1e-8f);
        o8[3] = s[3] - lse + __logf(p0.w + 1e-8f);
        o8[4] = s[4] - lse + __logf(p1.x + 1e-8f);
        o8[5] = s[5] - lse + __logf(p1.y + 1e-8f);
        o8[6] = s[6] - lse + __logf(p1.z + 1e-8f);
        o8[7] = s[7] - lse + __logf(p1.w + 1e-8f);

        if (mode == 1) {
            const int* mp = (const int*)maskraw;
#pragma unroll
            for (int j = 0; j < 8; j++) if (mp[base + j] == 0) o8[j] = NEG;
        } else if (mode == 2) {
            const float* mp = (const float*)maskraw;
#pragma unroll
            for (int j = 0; j < 8; j++) if (mp[base + j] == 0.f) o8[j] = NEG;
        } else {
            const uchar* mp = (const uchar*)maskraw;
            uchar4 m0 = *(const uchar4*)(mp + base);
            uchar4 m1 = *(const uchar4*)(mp + base + 4);
            if (!m0.x) o8[0] = NEG; if (!m0.y) o8[1] = NEG;
            if (!m0.z) o8[2] = NEG; if (!m0.w) o8[3] = NEG;
            if (!m1.x) o8[4] = NEG; if (!m1.y) o8[5] = NEG;
            if (!m1.z) o8[6] = NEG; if (!m1.w) o8[7] = NEG;
        }

        *(float4*)(out + base)     = make_float4(o8[0], o8[1], o8[2], o8[3]);
        *(float4*)(out + base + 4) = make_float4(o8[4], o8[5], o8[6], o8[7]);
        __syncwarp();
    }
}

// ---------------------------------------------------------------------------
extern "C" void kernel_launch(void* const* d_in, const int* in_sizes, int n_in,
                              void* d_out, int out_size)
{
    const float* phonemes = (const float*)d_in[0];
    const float* audio    = (const float*)d_in[1];
    const uchar* mask     = (const uchar*)d_in[2];
    const float* prior    = (const float*)d_in[3];
    const float* kw1 = (const float*)d_in[4];
    const float* kb1 = (const float*)d_in[5];
    const float* kw2 = (const float*)d_in[6];
    const float* kb2 = (const float*)d_in[7];
    const float* qw1 = (const float*)d_in[8];
    const float* qb1 = (const float*)d_in[9];
    const float* qw2 = (const float*)d_in[10];
    const float* qb2 = (const float*)d_in[11];
    const float* qw3 = (const float*)d_in[12];
    const float* qb3 = (const float*)d_in[13];
    float* out = (float*)d_out;

    void* p;
    cudaGetSymbolAddress(&p, g_wk1);    bf16* wk1 = (bf16*)p;
    cudaGetSymbolAddress(&p, g_wq1);    bf16* wq1 = (bf16*)p;
    cudaGetSymbolAddress(&p, g_wk2);    bf16* wk2 = (bf16*)p;
    cudaGetSymbolAddress(&p, g_wq2);    bf16* wq2 = (bf16*)p;
    cudaGetSymbolAddress(&p, g_wq3);    bf16* wq3 = (bf16*)p;
    cudaGetSymbolAddress(&p, g_phon);   bf16* phon = (bf16*)p;
    cudaGetSymbolAddress(&p, g_audio);  bf16* aud  = (bf16*)p;
    cudaGetSymbolAddress(&p, g_H1b);    bf16* H1 = (bf16*)p;
    cudaGetSymbolAddress(&p, g_H2b);    bf16* H2 = (bf16*)p;
    cudaGetSymbolAddress(&p, g_H3b);    bf16* H3 = (bf16*)p;
    cudaGetSymbolAddress(&p, g_keysP);  float* keysP = (float*)p;
    cudaGetSymbolAddress(&p, g_Q);      float* Q = (float*)p;

    const int SMEM_K3 = (2 * 128 * 56 + 2 * 48 * 136) * 2;  // 54784 (TN=128 config)
    const int SMEM_K1 = (2 * 128 * 40 + 2 * 32 * 72) * 2;   // 29696

    cudaFuncSetAttribute(conv3_dual,
                         cudaFuncAttributeMaxDynamicSharedMemorySize, SMEM_K3);

    // L1: prep (4 elems/thread)
    {
        long total = 1024L * 1536 + 160 * 240 + 80 * 1024 + 80 * 160 + 80 * 80
                   + 8L * 512 * 272 + 8L * 80 * 1040;
        prep_kernel<<<(int)((total / 4 + 255) / 256), 256>>>(
            kw1, qw1, kw2, qw2, qw3, phonemes, audio, mask);
    }

    // L2: kconv1 + qconv1 merged (R12-proven TN=128 config, 128 blocks each)
    {
        Job jk1 = { wk1, kb1, phon, (char*)H1, 1024, 256, 272, 1536, 1536, 2, 8, 1 | 2 };
        Job jq1 = { wq1, qb1, aud,  (char*)H2, 160, 1000, 1040, 240, 240, 8, 2, 1 | 2 };
        conv3_dual<<<128 + 128, 256, SMEM_K3>>>(jk1, jq1, 128);
    }

    // L3: kconv2 split-K x4 + qconv2 (merged)
    {
        Job jk2 = { wk2, kb2, H1, (char*)keysP, 80, 256, 256, 1024, 256, 4, 4, 4 };
        Job jq2 = { wq2, qb2, H2, (char*)H3, 80, 1000, 1000, 160, 160, 16, 1, 1 | 2 };
        conv1_multi<<<128 + 128, 256, SMEM_K1>>>(jk2, jq2, 128, 256, 0);
    }

    // L4: qconv3 + keys reduce x4 (merged)
    {
        Job jq3 = { wq3, qb3, H3, (char*)Q, 80, 1000, 1000, 80, 80, 16, 1, 0 };
        conv1_multi<<<128 + 160, 256, SMEM_K1>>>(jq3, jq3, 128, 128, 4);
    }

    // L5: attention + log_softmax + prior + mask
    attn_kernel<<<dim3(25, 8), 256>>>(prior, mask, out);
}

// round 17
// speedup vs baseline: 1.3685x; 1.2590x over previous
#include <cuda_runtime.h>
#include <cuda_bf16.h>
#include <cstdint>

typedef unsigned char uchar;
typedef unsigned short ushort;
typedef __nv_bfloat16 bf16;

#define NB 8

// ---------------- device scratch ----------------
__device__ __align__(16) bf16 g_wk1[1024 * 1536];
__device__ __align__(16) bf16 g_wq1[160 * 240];
__device__ __align__(16) bf16 g_wk2[80 * 1024];
__device__ __align__(16) bf16 g_wq2[80 * 160];
__device__ __align__(16) bf16 g_wq3[80 * 80];
__device__ __align__(16) bf16 g_phon [NB * 512 * 272];     // halo-padded, XS=272
__device__ __align__(16) bf16 g_audio[NB * 80 * 1040];     // halo-padded, XS=1040
__device__ __align__(16) bf16 g_H1b[NB * 1024 * 256];
__device__ __align__(16) bf16 g_H2b[NB * 160 * 1000 + 64];
__device__ __align__(16) bf16 g_H3b[NB * 80 * 1000 + 64];
__device__ __align__(16) float g_keysP[4 * NB * 80 * 256]; // split-K partials (x4)
__device__ __align__(16) bf16  g_keysBf[NB * 80 * 256];
__device__ __align__(16) bf16  g_Qt[NB * 1000 * 80 + 64];  // Q transposed [b][t][c] bf16
__device__ int g_maskmode;                                 // 0=u8, 1=i32, 2=f32

union U8 { uint4 v; ushort u[8]; };

// ---------------- fused prep (4 elems/thread): convert + pad + mask detect --
__global__ void prep_kernel(
    const float* __restrict__ kw1, const float* __restrict__ qw1,
    const float* __restrict__ kw2, const float* __restrict__ qw2,
    const float* __restrict__ qw3, const float* __restrict__ phon,
    const float* __restrict__ aud, const uchar* __restrict__ mask)
{
    if (blockIdx.x == 0 && threadIdx.x == 0) {
        const unsigned* d = (const unsigned*)mask;
        bool i32 = true, f32 = true;
        for (int i = 0; i < 256; i++) {
            unsigned v = d[i];
            if (v != 0u && v != 1u) i32 = false;
            if (v != 0u && v != 0x3F800000u) f32 = false;
        }
        g_maskmode = i32 ? 1 : (f32 ? 2 : 0);
    }
    long i = ((long)blockIdx.x * 256 + threadIdx.x) * 4;
    const long N1 = 1024L * 1536, N2 = 160 * 240, N3 = 80 * 1024,
               N4 = 80 * 160, N5 = 80 * 80;
    const long NP = 8L * 512 * 272, NA = 8L * 80 * 1040;

    const float* src = nullptr; bf16* dst = nullptr;
    if (i < N1) { src = kw1; dst = g_wk1; }
    else if ((i -= N1) < N2) { src = qw1; dst = g_wq1; }
    else if ((i -= N2) < N3) { src = kw2; dst = g_wk2; }
    else if ((i -= N3) < N4) { src = qw2; dst = g_wq2; }
    else if ((i -= N4) < N5) { src = qw3; dst = g_wq3; }
    if (src) {
        float4 v = *(const float4*)(src + i);
        *(__nv_bfloat162*)(dst + i)     = __floats2bfloat162_rn(v.x, v.y);
        *(__nv_bfloat162*)(dst + i + 2) = __floats2bfloat162_rn(v.z, v.w);
        return;
    }
    i -= N5;
    if (i < NP) {   // phonemes: rows of 272, valid x in [1,256]
        long r = i / 272; int x0 = (int)(i - r * 272);
#pragma unroll
        for (int e = 0; e < 4; e++) {
            int x = x0 + e;
            g_phon[i + e] = (x >= 1 && x <= 256)
                ? __float2bfloat16(phon[r * 256 + x - 1]) : __float2bfloat16(0.f);
        }
        return;
    }
    i -= NP;
    if (i < NA) {   // audio: rows of 1040, valid x in [1,1000]
        long r = i / 1040; int x0 = (int)(i - r * 1040);
#pragma unroll
        for (int e = 0; e < 4; e++) {
            int x = x0 + e;
            g_audio[i + e] = (x >= 1 && x <= 1000)
                ? __float2bfloat16(aud[r * 1000 + x - 1]) : __float2bfloat16(0.f);
        }
    }
}

// ---------------- mma / cp.async helpers ----------------
__device__ __forceinline__ uint32_t smem_u32(const void* p) {
    return (uint32_t)__cvta_generic_to_shared(p);
}
__device__ __forceinline__ void cpasync16(uint32_t dst, const void* src, int szbytes) {
    asm volatile("cp.async.cg.shared.global [%0], [%1], 16, %2;"
                 :: "r"(dst), "l"(src), "r"(szbytes) : "memory");
}
#define CP_COMMIT() asm volatile("cp.async.commit_group;" ::: "memory")
#define CP_WAIT0()  asm volatile("cp.async.wait_group 0;" ::: "memory")

__device__ __forceinline__ void ldsm4(uint32_t& r0, uint32_t& r1,
                                      uint32_t& r2, uint32_t& r3, uint32_t a) {
    asm volatile("ldmatrix.sync.aligned.m8n8.x4.shared.b16 {%0,%1,%2,%3}, [%4];"
                 : "=r"(r0), "=r"(r1), "=r"(r2), "=r"(r3) : "r"(a));
}
__device__ __forceinline__ void ldsm4t(uint32_t& r0, uint32_t& r1,
                                       uint32_t& r2, uint32_t& r3, uint32_t a) {
    asm volatile("ldmatrix.sync.aligned.m8n8.x4.trans.shared.b16 {%0,%1,%2,%3}, [%4];"
                 : "=r"(r0), "=r"(r1), "=r"(r2), "=r"(r3) : "r"(a));
}
__device__ __forceinline__ void mma16816(float c[4], const uint32_t a[4],
                                         uint32_t b0, uint32_t b1) {
    asm volatile(
        "mma.sync.aligned.m16n8k16.row.col.f32.bf16.bf16.f32 "
        "{%0,%1,%2,%3}, {%4,%5,%6,%7}, {%8,%9}, {%0,%1,%2,%3};"
        : "+f"(c[0]), "+f"(c[1]), "+f"(c[2]), "+f"(c[3])
        : "r"(a[0]), "r"(a[1]), "r"(a[2]), "r"(a[3]), "r"(b0), "r"(b1));
}

template <int BSTR, int TN>
__device__ __forceinline__ void storeB3(ushort* Brow, int pbase, uint4 v) {
    U8 u; u.v = v;
#pragma unroll
    for (int kw = 0; kw < 3; kw++)
#pragma unroll
        for (int j = 0; j < 8; j++) {
            int t = pbase + j - kw;
            if (t >= 0 && t < TN) Brow[kw * BSTR + t] = u.u[j];
        }
}

// ---------------- job descriptor ----------------
// flags: 1=relu, 2=outBf16, 4=split, 16=transposed bf16 out Y[b][t][M]
struct Job {
    const bf16* W; const float* bias; const bf16* X; char* Y;
    int M, T, XS, Ktot, kLen, nbx, nby, flags;
};

// ---------------------------------------------------------------------------
// Pipelined bf16 tensor-core conv-as-GEMM body (cp.async staging, R16-proven).
// ---------------------------------------------------------------------------
template <int KW, int TKC, int TN, int WMI, int WNJ>
__device__ __forceinline__ void conv_body(const Job j, int bx, int by, int b)
{
    constexpr int TM = 128;
    constexpr int TK = TKC * KW;
    constexpr int KSTEPS = TK / 16;
    constexpr int ASTR = TK + 8;
    constexpr int BSTR = TN + 8;
    constexpr int WARPSN = TN / (16 * WNJ);
    constexpr int ACH = (TM * TK) / 2048;
    constexpr int AKCH = TK / 8;

    extern __shared__ __align__(16) bf16 dsm[];
    bf16* Asm = dsm;
    bf16* Bsm = dsm + 2 * TM * ASTR;

    const bool relu = j.flags & 1, outBf = j.flags & 2, split = j.flags & 4;
    const bool outTr = j.flags & 16;
    const int tid = threadIdx.x, lane = tid & 31, wid = tid >> 5;
    const int m0 = split ? 0 : by * TM;
    const int kb = split ? by * j.kLen : 0;
    const int kLim = min(kb + j.kLen, j.Ktot);
    const int Cin = j.Ktot / KW;
    const int t0 = bx * TN;
    const int wm = (wid / WARPSN) * (WMI * 16);
    const int wn = (wid % WARPSN) * (WNJ * 16);
    const bf16* Xb = j.X + (long)b * Cin * j.XS;
    const int Ktot = j.Ktot, M = j.M, T = j.T, XS = j.XS;

    const uint32_t AsU = smem_u32(Asm);
    const uint32_t BsU = smem_u32(Bsm);

    float acc[WMI][WNJ * 2][4];
#pragma unroll
    for (int mi = 0; mi < WMI; mi++)
#pragma unroll
        for (int jj = 0; jj < WNJ * 2; jj++)
#pragma unroll
            for (int c = 0; c < 4; c++) acc[mi][jj][c] = 0.f;

    const int iters = (kLim - kb + TK - 1) / TK;

    uint4 bR0, bR1;
    constexpr int CHB = (TN + 16) / 8;

    auto issueA = [&](int it, int p) {
#pragma unroll
        for (int r = 0; r < ACH; r++) {
            int cid = tid + 256 * r;
            int row = cid / AKCH;
            int ch  = (cid % AKCH) * 8;
            int gm = m0 + row;
            int gk = kb + it * TK + ch;
            bool ok = (gm < M && gk < kLim);
            const bf16* src = j.W + (ok ? ((long)gm * Ktot + gk) : 0);
            cpasync16(AsU + (uint32_t)(p * TM * ASTR + row * ASTR + ch) * 2,
                      src, ok ? 16 : 0);
        }
    };
    auto issueB1 = [&](int it, int p) {
        int kk = tid >> 3, seg = tid & 7;
        int c = kb + it * TK + kk;
        bool ok = (c < kLim);
        const bf16* src = Xb + (ok ? ((long)c * XS + t0 + seg * 8) : 0);
        cpasync16(BsU + (uint32_t)(p * TK * BSTR + kk * BSTR + seg * 8) * 2,
                  src, ok ? 16 : 0);
    };
    auto loadB3 = [&](int it) {
        int r = tid >> 4, seg = tid & 15;
        const bf16* rowp = Xb + (long)(it * TKC + r) * XS + t0;
        if (seg < CHB) bR0 = *(const uint4*)(rowp + seg * 8);
        if constexpr (CHB > 16) {
            if (seg + 16 < CHB) bR1 = *(const uint4*)(rowp + (seg + 16) * 8);
        }
    };
    auto storeB3s = [&](int p) {
        int r = tid >> 4, seg = tid & 15;
        ushort* Brow = (ushort*)(Bsm + p * TK * BSTR + (r * 3) * BSTR);
        if (seg < CHB) storeB3<BSTR, TN>(Brow, seg * 8, bR0);
        if constexpr (CHB > 16) {
            if (seg + 16 < CHB) storeB3<BSTR, TN>(Brow, (seg + 16) * 8, bR1);
        }
    };
    auto compute = [&](int p) {
#pragma unroll
        for (int ks = 0; ks < KSTEPS; ks++) {
            uint32_t a[WMI][4];
#pragma unroll
            for (int mi = 0; mi < WMI; mi++) {
                uint32_t addr = AsU + (uint32_t)(p * TM * ASTR +
                    (wm + mi * 16 + (lane & 15)) * ASTR + ks * 16 + (lane >> 4) * 8) * 2;
                ldsm4(a[mi][0], a[mi][1], a[mi][2], a[mi][3], addr);
            }
            uint32_t bb[WNJ][4];
#pragma unroll
            for (int nj = 0; nj < WNJ; nj++) {
                uint32_t addr = BsU + (uint32_t)(p * TK * BSTR +
                    (ks * 16 + (lane & 15)) * BSTR + wn + nj * 16 + (lane >> 4) * 8) * 2;
                ldsm4t(bb[nj][0], bb[nj][1], bb[nj][2], bb[nj][3], addr);
            }
#pragma unroll
            for (int mi = 0; mi < WMI; mi++)
#pragma unroll
                for (int nj = 0; nj < WNJ; nj++) {
                    mma16816(acc[mi][nj * 2 + 0], a[mi], bb[nj][0], bb[nj][1]);
                    mma16816(acc[mi][nj * 2 + 1], a[mi], bb[nj][2], bb[nj][3]);
                }
        }
    };

    issueA(0, 0);
    if constexpr (KW == 1) issueB1(0, 0); else loadB3(0);
    CP_COMMIT();
    if constexpr (KW == 3) storeB3s(0);
    CP_WAIT0();
    __syncthreads();

    for (int it = 0; it < iters; it++) {
        int p = it & 1;
        if (it + 1 < iters) {
            issueA(it + 1, 1 - p);
            if constexpr (KW == 1) issueB1(it + 1, 1 - p); else loadB3(it + 1);
            CP_COMMIT();
        }
        compute(p);
        if (it + 1 < iters) {
            if constexpr (KW == 3) storeB3s(1 - p);
            CP_WAIT0();
            __syncthreads();
        }
    }

    // epilogue
    const int g = lane >> 2, tig = lane & 3;
#pragma unroll
    for (int mi = 0; mi < WMI; mi++)
#pragma unroll
        for (int h = 0; h < 2; h++) {
            int gm = m0 + wm + mi * 16 + g + h * 8;
            if (gm >= M) continue;
            float bv = (split && by != 0) ? 0.f : j.bias[gm];
            long rowoff = 0;
            if (!outTr) {
                if (split) rowoff = ((long)(by * NB + b) * M + gm) * T;
                else       rowoff = ((long)b * M + gm) * T;
            }
#pragma unroll
            for (int jj = 0; jj < WNJ * 2; jj++) {
                int t = t0 + wn + jj * 8 + tig * 2;
                float v0 = acc[mi][jj][h * 2 + 0] + bv;
                float v1 = acc[mi][jj][h * 2 + 1] + bv;
                if (relu) { v0 = fmaxf(v0, 0.f); v1 = fmaxf(v1, 0.f); }
                if (outTr) {
                    bf16* Yt = (bf16*)j.Y + (long)b * T * M + gm;
                    if (t < T)     Yt[(long)t * M]       = __float2bfloat16(v0);
                    if (t + 1 < T) Yt[(long)(t + 1) * M] = __float2bfloat16(v1);
                } else {
                    if (t >= T) continue;
                    if (outBf)
                        *(__nv_bfloat162*)((bf16*)j.Y + rowoff + t) = __floats2bfloat162_rn(v0, v1);
                    else
                        *(float2*)((float*)j.Y + rowoff + t) = make_float2(v0, v1);
                }
            }
        }
}

__device__ __forceinline__ void decode(const Job& j, int local, int& bx, int& by, int& bz)
{
    bx = local % j.nbx;
    int rem = local / j.nbx;
    by = rem % j.nby;
    bz = rem / j.nby;
}

// L2: both k=3 convs in one launch (R12-proven TN=128, warp tile 64x32)
__global__ void __launch_bounds__(256) conv3_dual(Job j0, Job j1, int n0)
{
    int bid = blockIdx.x;
    Job j = (bid < n0) ? j0 : j1;
    int local = (bid < n0) ? bid : bid - n0;
    int bx, by, bz; decode(j, local, bx, by, bz);
    conv_body<3, 16, 128, 4, 2>(j, bx, by, bz);
}

// L3/L4: 1x1 convs (+ optional keys split-K reduce blocks at the tail)
__global__ void __launch_bounds__(256) conv1_multi(Job j0, Job j1, int n0, int ntot, int nParts)
{
    int bid = blockIdx.x;
    if (bid >= ntot) {      // reduce blocks
        int i = ((bid - ntot) * 256 + threadIdx.x) * 4;
        const int N = NB * 80 * 256;
        if (i < N) {
            float4 s = *(const float4*)&g_keysP[i];
            for (int p = 1; p < nParts; p++) {
                float4 t = *(const float4*)&g_keysP[(long)p * N + i];
                s.x += t.x; s.y += t.y; s.z += t.z; s.w += t.w;
            }
            __nv_bfloat162* dst = (__nv_bfloat162*)&g_keysBf[i];
            dst[0] = __floats2bfloat162_rn(s.x, s.y);
            dst[1] = __floats2bfloat162_rn(s.z, s.w);
        }
        return;
    }
    Job j = (bid < n0) ? j0 : j1;
    int local = (bid < n0) ? bid : bid - n0;
    int bx, by, bz; decode(j, local, bx, by, bz);
    conv_body<1, 32, 64, 2, 2>(j, bx, by, bz);
}

// ---------------------------------------------------------------------------
// Tensor-core attention: scores via bf16 mma (fp32 accum), row log-softmax,
// + log(prior+1e-8), mask -> -inf.  Block = 64 t-rows x 256 keys, K=80.
// 8 warps as 2(t) x 4(s); warp tile 32x64.  q^2 cancels in log_softmax.
// ---------------------------------------------------------------------------
#define ATTN_SMEM ((80 * 264 + 64 * 88) * 2 + 256 * 4 + 64 * 4 * 4 * 2)

__global__ void __launch_bounds__(256) attn_mma_kernel(
    const float* __restrict__ prior, const void* __restrict__ maskraw,
    float* __restrict__ out)
{
    extern __shared__ __align__(16) char asm_[];
    bf16*  ks   = (bf16*)asm_;                 // [80][264]
    bf16*  qa   = ks + 80 * 264;               // [64][88]
    float* k2s  = (float*)(qa + 64 * 88);      // [256]
    float* redM = k2s + 256;                   // [64][4]
    float* redS = redM + 256;                  // [64][4]

    const int b  = blockIdx.y;
    const int t0 = blockIdx.x * 64;
    const int tid = threadIdx.x, lane = tid & 31, wid = tid >> 5;
    const int g = lane >> 2, tig = lane & 3;
    const int wm = (wid >> 2) * 32;            // t-offset in tile
    const int wn = (wid & 3) * 64;             // s-offset
    const int swid = wid & 3;
    const int mode = g_maskmode;

    // ---- load keys [80][256] and Q-tile [64][80] ----
    const bf16* keysb = g_keysBf + (long)b * 80 * 256;
    for (int cid = tid; cid < 80 * 32; cid += 256) {
        int row = cid >> 5, seg = cid & 31;
        *(uint4*)(ks + row * 264 + seg * 8) = *(const uint4*)(keysb + row * 256 + seg * 8);
    }
    for (int cid = tid; cid < 64 * 10; cid += 256) {
        int r = cid / 10, ch = (cid % 10) * 8;
        int t = t0 + r;
        uint4 v = make_uint4(0u, 0u, 0u, 0u);
        if (t < 1000) v = *(const uint4*)(g_Qt + ((long)b * 1000 + t) * 80 + ch);
        *(uint4*)(qa + r * 88 + ch) = v;
    }
    __syncthreads();

    // ---- |k|^2 per key (from bf16 keys) ----
    {
        float s = 0.f;
#pragma unroll 8
        for (int c = 0; c < 80; c++) {
            float v = __bfloat162float(ks[c * 264 + tid]);
            s += v * v;
        }
        k2s[tid] = s;
    }

    // ---- GEMM: acc[t, s] = sum_c q[t,c] * k[c,s]  (5 k16-steps) ----
    const uint32_t QaU = smem_u32(qa);
    const uint32_t KsU = smem_u32(ks);
    float acc[2][8][4];
#pragma unroll
    for (int mi = 0; mi < 2; mi++)
#pragma unroll
        for (int jj = 0; jj < 8; jj++)
#pragma unroll
            for (int c = 0; c < 4; c++) acc[mi][jj][c] = 0.f;

#pragma unroll
    for (int kstep = 0; kstep < 5; kstep++) {
        uint32_t a[2][4];
#pragma unroll
        for (int mi = 0; mi < 2; mi++) {
            uint32_t addr = QaU + (uint32_t)(
                (wm + mi * 16 + (lane & 15)) * 88 + kstep * 16 + (lane >> 4) * 8) * 2;
            ldsm4(a[mi][0], a[mi][1], a[mi][2], a[mi][3], addr);
        }
        uint32_t bb[4][4];
#pragma unroll
        for (int nj = 0; nj < 4; nj++) {
            uint32_t addr = KsU + (uint32_t)(
                (kstep * 16 + (lane & 15)) * 264 + wn + nj * 16 + (lane >> 4) * 8) * 2;
            ldsm4t(bb[nj][0], bb[nj][1], bb[nj][2], bb[nj][3], addr);
        }
#pragma unroll
        for (int mi = 0; mi < 2; mi++)
#pragma unroll
            for (int nj = 0; nj < 4; nj++) {
                mma16816(acc[mi][nj * 2 + 0], a[mi], bb[nj][0], bb[nj][1]);
                mma16816(acc[mi][nj * 2 + 1], a[mi], bb[nj][2], bb[nj][3]);
            }
    }
    __syncthreads();   // k2s complete before epilogue reads it

    // score s(t, col) = T * (2*acc - k2[col]);  T = 0.0005
    // ---- row max: local -> quad shfl -> cross-warp via smem ----
    float mx[2][2] = {{-1e30f, -1e30f}, {-1e30f, -1e30f}};
#pragma unroll
    for (int mi = 0; mi < 2; mi++)
#pragma unroll
        for (int jj = 0; jj < 8; jj++) {
            int col = wn + jj * 8 + tig * 2;
            float k0 = k2s[col], k1 = k2s[col + 1];
#pragma unroll
            for (int h = 0; h < 2; h++) {
                float s0 = 0.0005f * (2.f * acc[mi][jj][h * 2 + 0] - k0);
                float s1 = 0.0005f * (2.f * acc[mi][jj][h * 2 + 1] - k1);
                mx[mi][h] = fmaxf(mx[mi][h], fmaxf(s0, s1));
            }
        }
#pragma unroll
    for (int o = 1; o <= 2; o <<= 1) {
#pragma unroll
        for (int mi = 0; mi < 2; mi++)
#pragma unroll
            for (int h = 0; h < 2; h++)
                mx[mi][h] = fmaxf(mx[mi][h], __shfl_xor_sync(0xffffffffu, mx[mi][h], o));
    }
    if (tig == 0) {
#pragma unroll
        for (int mi = 0; mi < 2; mi++)
#pragma unroll
            for (int h = 0; h < 2; h++)
                redM[(wm + mi * 16 + g + h * 8) * 4 + swid] = mx[mi][h];
    }
    __syncthreads();
    float rmax[2][2];
#pragma unroll
    for (int mi = 0; mi < 2; mi++)
#pragma unroll
        for (int h = 0; h < 2; h++) {
            const float* rp = redM + (wm + mi * 16 + g + h * 8) * 4;
            rmax[mi][h] = fmaxf(fmaxf(rp[0], rp[1]), fmaxf(rp[2], rp[3]));
        }

    // ---- row sum of exp ----
    float sm[2][2] = {{0.f, 0.f}, {0.f, 0.f}};
#pragma unroll
    for (int mi = 0; mi < 2; mi++)
#pragma unroll
        for (int jj = 0; jj < 8; jj++) {
            int col = wn + jj * 8 + tig * 2;
            float k0 = k2s[col], k1 = k2s[col + 1];
#pragma unroll
            for (int h = 0; h < 2; h++) {
                float s0 = 0.0005f * (2.f * acc[mi][jj][h * 2 + 0] - k0);
                float s1 = 0.0005f * (2.f * acc[mi][jj][h * 2 + 1] - k1);
                sm[mi][h] += __expf(s0 - rmax[mi][h]) + __expf(s1 - rmax[mi][h]);
            }
        }
#pragma unroll
    for (int o = 1; o <= 2; o <<= 1) {
#pragma unroll
        for (int mi = 0; mi < 2; mi++)
#pragma unroll
            for (int h = 0; h < 2; h++)
                sm[mi][h] += __shfl_xor_sync(0xffffffffu, sm[mi][h], o);
    }
    if (tig == 0) {
#pragma unroll
        for (int mi = 0; mi < 2; mi++)
#pragma unroll
            for (int h = 0; h < 2; h++)
                redS[(wm + mi * 16 + g + h * 8) * 4 + swid] = sm[mi][h];
    }
    __syncthreads();

    // ---- output: s - lse + log(prior + 1e-8); mask -> -inf ----
    const float NEG = __int_as_float(0xff800000);
#pragma unroll
    for (int mi = 0; mi < 2; mi++)
#pragma unroll
        for (int h = 0; h < 2; h++) {
            int trow = t0 + wm + mi * 16 + g + h * 8;
            if (trow >= 1000) continue;
            const float* sp = redS + (wm + mi * 16 + g + h * 8) * 4;
            float lse = rmax[mi][h] + __logf(sp[0] + sp[1] + sp[2] + sp[3]);
            long base = ((long)(b * 1000 + trow)) * 256;
#pragma unroll
            for (int jj = 0; jj < 8; jj++) {
                int col = wn + jj * 8 + tig * 2;
                float s0 = 0.0005f * (2.f * acc[mi][jj][h * 2 + 0] - k2s[col]);
                float s1 = 0.0005f * (2.f * acc[mi][jj][h * 2 + 1] - k2s[col + 1]);
                float2 pr = *(const float2*)(prior + base + col);
                float o0 = s0 - lse + __logf(pr.x + 1e-8f);
                float o1 = s1 - lse + __logf(pr.y + 1e-8f);
                if (mode == 1) {
                    const int* mp = (const int*)maskraw + base + col;
                    if (mp[0] == 0) o0 = NEG;
                    if (mp[1] == 0) o1 = NEG;
                } else if (mode == 2) {
                    const float* mp = (const float*)maskraw + base + col;
                    if (mp[0] == 0.f) o0 = NEG;
                    if (mp[1] == 0.f) o1 = NEG;
                } else {
                    const uchar* mp = (const uchar*)maskraw + base + col;
                    if (!mp[0]) o0 = NEG;
                    if (!mp[1]) o1 = NEG;
                }
                *(float2*)(out + base + col) = make_float2(o0, o1);
            }
        }
}

// ---------------------------------------------------------------------------
extern "C" void kernel_launch(void* const* d_in, const int* in_sizes, int n_in,
                              void* d_out, int out_size)
{
    const float* phonemes = (const float*)d_in[0];
    const float* audio    = (const float*)d_in[1];
    const uchar* mask     = (const uchar*)d_in[2];
    const float* prior    = (const float*)d_in[3];
    const float* kw1 = (const float*)d_in[4];
    const float* kb1 = (const float*)d_in[5];
    const float* kw2 = (const float*)d_in[6];
    const float* kb2 = (const float*)d_in[7];
    const float* qw1 = (const float*)d_in[8];
    const float* qb1 = (const float*)d_in[9];
    const float* qw2 = (const float*)d_in[10];
    const float* qb2 = (const float*)d_in[11];
    const float* qw3 = (const float*)d_in[12];
    const float* qb3 = (const float*)d_in[13];
    float* out = (float*)d_out;

    void* p;
    cudaGetSymbolAddress(&p, g_wk1);    bf16* wk1 = (bf16*)p;
    cudaGetSymbolAddress(&p, g_wq1);    bf16* wq1 = (bf16*)p;
    cudaGetSymbolAddress(&p, g_wk2);    bf16* wk2 = (bf16*)p;
    cudaGetSymbolAddress(&p, g_wq2);    bf16* wq2 = (bf16*)p;
    cudaGetSymbolAddress(&p, g_wq3);    bf16* wq3 = (bf16*)p;
    cudaGetSymbolAddress(&p, g_phon);   bf16* phon = (bf16*)p;
    cudaGetSymbolAddress(&p, g_audio);  bf16* aud  = (bf16*)p;
    cudaGetSymbolAddress(&p, g_H1b);    bf16* H1 = (bf16*)p;
    cudaGetSymbolAddress(&p, g_H2b);    bf16* H2 = (bf16*)p;
    cudaGetSymbolAddress(&p, g_H3b);    bf16* H3 = (bf16*)p;
    cudaGetSymbolAddress(&p, g_keysP);  float* keysP = (float*)p;
    cudaGetSymbolAddress(&p, g_Qt);     bf16* Qt = (bf16*)p;

    const int SMEM_K3 = (2 * 128 * 56 + 2 * 48 * 136) * 2;  // 54784 (TN=128 config)
    const int SMEM_K1 = (2 * 128 * 40 + 2 * 32 * 72) * 2;   // 29696

    cudaFuncSetAttribute(conv3_dual,
                         cudaFuncAttributeMaxDynamicSharedMemorySize, SMEM_K3);
    cudaFuncSetAttribute(attn_mma_kernel,
                         cudaFuncAttributeMaxDynamicSharedMemorySize, ATTN_SMEM);

    // L1: prep (4 elems/thread)
    {
        long total = 1024L * 1536 + 160 * 240 + 80 * 1024 + 80 * 160 + 80 * 80
                   + 8L * 512 * 272 + 8L * 80 * 1040;
        prep_kernel<<<(int)((total / 4 + 255) / 256), 256>>>(
            kw1, qw1, kw2, qw2, qw3, phonemes, audio, mask);
    }

    // L2: kconv1 + qconv1 merged (R12-proven TN=128 config, 128 blocks each)
    {
        Job jk1 = { wk1, kb1, phon, (char*)H1, 1024, 256, 272, 1536, 1536, 2, 8, 1 | 2 };
        Job jq1 = { wq1, qb1, aud,  (char*)H2, 160, 1000, 1040, 240, 240, 8, 2, 1 | 2 };
        conv3_dual<<<128 + 128, 256, SMEM_K3>>>(jk1, jq1, 128);
    }

    // L3: kconv2 split-K x4 + qconv2 (merged)
    {
        Job jk2 = { wk2, kb2, H1, (char*)keysP, 80, 256, 256, 1024, 256, 4, 4, 4 };
        Job jq2 = { wq2, qb2, H2, (char*)H3, 80, 1000, 1000, 160, 160, 16, 1, 1 | 2 };
        conv1_multi<<<128 + 128, 256, SMEM_K1>>>(jk2, jq2, 128, 256, 0);
    }

    // L4: qconv3 (transposed bf16 out -> Qt) + keys reduce x4 (merged)
    {
        Job jq3 = { wq3, qb3, H3, (char*)Qt, 80, 1000, 1000, 80, 80, 16, 1, 16 };
        conv1_multi<<<128 + 160, 256, SMEM_K1>>>(jq3, jq3, 128, 128, 4);
    }

    // L5: tensor-core attention + log_softmax + prior + mask
    attn_mma_kernel<<<dim3(16, 8), 256, ATTN_SMEM>>>(prior, mask, out);
}